// round 12
// baseline (speedup 1.0000x reference)
#include <cuda_runtime.h>
#include <cuda_bf16.h>
#include <cuda_fp16.h>
#include <cstdint>

#define B_ 2048
#define T_ 256
#define F_ 64
#define H_ 32
#define G_ 96

// scratch: xg[B*T][96] fp16 (100 MB)
__device__ __half g_xg[(size_t)B_ * T_ * G_];

__device__ __forceinline__ uint32_t smem_u32(const void* p) {
    uint32_t a;
    asm("{ .reg .u64 t; cvta.to.shared.u64 t, %1; cvt.u32.u64 %0, t; }" : "=r"(a) : "l"(p));
    return a;
}
__device__ __forceinline__ float tanh_fast(float v) {
    float y; asm("tanh.approx.f32 %0, %1;" : "=f"(y) : "f"(v)); return y;
}
__device__ __forceinline__ float sigmoid_fast(float a) {
    return fmaf(tanh_fast(0.5f * a), 0.5f, 0.5f);
}
__device__ __forceinline__ uint64_t ffma2(uint64_t a, uint64_t b, uint64_t c) {
    uint64_t d;
    asm("fma.rn.f32x2 %0, %1, %2, %3;" : "=l"(d) : "l"(a), "l"(b), "l"(c));
    return d;
}
__device__ __forceinline__ float f2lo(uint64_t v) { return __uint_as_float((uint32_t)v); }
__device__ __forceinline__ float f2hi(uint64_t v) { return __uint_as_float((uint32_t)(v >> 32)); }
__device__ __forceinline__ uint32_t pack_bf16(float a, float b) {
    __nv_bfloat162 t = __floats2bfloat162_rn(a, b);
    return *reinterpret_cast<uint32_t*>(&t);
}

// ================= Phase 1: xg = x @ W_ih^T + b_ih  (mma.sync bf16, 3-pass split) ===========
#define PM 128
#define AROW 144
#define AH_OFF 0
#define AL_OFF (PM * AROW)
#define BH_OFF (2 * PM * AROW)
#define BL_OFF (BH_OFF + G_ * AROW)
#define SMEM_P1 (BL_OFF + G_ * AROW)
#define STRIDE_ST 100

__device__ __forceinline__ void mma_bf16(float* d, uint32_t a0, uint32_t a1, uint32_t a2,
                                         uint32_t a3, uint32_t b0, uint32_t b1) {
    asm("mma.sync.aligned.m16n8k16.row.col.f32.bf16.bf16.f32 "
        "{%0,%1,%2,%3}, {%4,%5,%6,%7}, {%8,%9}, {%0,%1,%2,%3};"
        : "+f"(d[0]), "+f"(d[1]), "+f"(d[2]), "+f"(d[3])
        : "r"(a0), "r"(a1), "r"(a2), "r"(a3), "r"(b0), "r"(b1));
}
__device__ __forceinline__ void split4(float4 v, uint2& hp, uint2& lp) {
    __nv_bfloat16 h0 = __float2bfloat16(v.x), h1 = __float2bfloat16(v.y);
    __nv_bfloat16 h2 = __float2bfloat16(v.z), h3 = __float2bfloat16(v.w);
    hp.x = pack_bf16(__bfloat162float(h0), __bfloat162float(h1));
    hp.y = pack_bf16(__bfloat162float(h2), __bfloat162float(h3));
    lp.x = pack_bf16(v.x - __bfloat162float(h0), v.y - __bfloat162float(h1));
    lp.y = pack_bf16(v.z - __bfloat162float(h2), v.w - __bfloat162float(h3));
}

__global__ __launch_bounds__(256, 3)
void proj_kernel(const float* __restrict__ x,
                 const float* __restrict__ W_ih,
                 const float* __restrict__ b_ih,
                 __half* __restrict__ xg)
{
    extern __shared__ __align__(16) char dsm[];
    __shared__ __align__(16) float sbias[G_];

    const int tid  = threadIdx.x;
    const int wid  = tid >> 5;
    const int lane = tid & 31;
    const int g    = lane >> 2;
    const int tg   = lane & 3;
    const size_t base = (size_t)blockIdx.x * PM;

    {
        const float4* xin = reinterpret_cast<const float4*>(x + base * F_);
        #pragma unroll
        for (int it = 0; it < PM * F_ / 4 / 256; it++) {
            int i = tid + it * 256;
            float4 v = xin[i];
            int row = i >> 4, c4 = i & 15;
            uint2 hp, lp; split4(v, hp, lp);
            uint32_t off = row * AROW + c4 * 8;
            *reinterpret_cast<uint2*>(dsm + AH_OFF + off) = hp;
            *reinterpret_cast<uint2*>(dsm + AL_OFF + off) = lp;
        }
    }
    {
        const float4* win = reinterpret_cast<const float4*>(W_ih);
        #pragma unroll
        for (int it = 0; it < G_ * F_ / 4 / 256; it++) {
            int i = tid + it * 256;
            float4 v = win[i];
            int row = i >> 4, c4 = i & 15;
            uint2 hp, lp; split4(v, hp, lp);
            uint32_t off = row * AROW + c4 * 8;
            *reinterpret_cast<uint2*>(dsm + BH_OFF + off) = hp;
            *reinterpret_cast<uint2*>(dsm + BL_OFF + off) = lp;
        }
    }
    if (tid < G_) sbias[tid] = b_ih[tid];
    __syncthreads();

    const int m0 = wid * 16;
    float acc[12][4];
    #pragma unroll
    for (int n = 0; n < 12; n++)
        #pragma unroll
        for (int q = 0; q < 4; q++) acc[n][q] = 0.f;

    const uint32_t arow0 = (m0 + g) * AROW;
    const uint32_t arow1 = (m0 + g + 8) * AROW;

    #pragma unroll
    for (int k = 0; k < 4; k++) {
        const uint32_t c0 = (k * 16 + 2 * tg) * 2;
        const uint32_t c1 = c0 + 16;
        uint32_t ah0 = *reinterpret_cast<const uint32_t*>(dsm + AH_OFF + arow0 + c0);
        uint32_t ah1 = *reinterpret_cast<const uint32_t*>(dsm + AH_OFF + arow1 + c0);
        uint32_t ah2 = *reinterpret_cast<const uint32_t*>(dsm + AH_OFF + arow0 + c1);
        uint32_t ah3 = *reinterpret_cast<const uint32_t*>(dsm + AH_OFF + arow1 + c1);
        uint32_t al0 = *reinterpret_cast<const uint32_t*>(dsm + AL_OFF + arow0 + c0);
        uint32_t al1 = *reinterpret_cast<const uint32_t*>(dsm + AL_OFF + arow1 + c0);
        uint32_t al2 = *reinterpret_cast<const uint32_t*>(dsm + AL_OFF + arow0 + c1);
        uint32_t al3 = *reinterpret_cast<const uint32_t*>(dsm + AL_OFF + arow1 + c1);
        #pragma unroll
        for (int n = 0; n < 12; n++) {
            const uint32_t brow = (n * 8 + g) * AROW;
            uint32_t bh0 = *reinterpret_cast<const uint32_t*>(dsm + BH_OFF + brow + c0);
            uint32_t bh1 = *reinterpret_cast<const uint32_t*>(dsm + BH_OFF + brow + c1);
            uint32_t bl0 = *reinterpret_cast<const uint32_t*>(dsm + BL_OFF + brow + c0);
            uint32_t bl1 = *reinterpret_cast<const uint32_t*>(dsm + BL_OFF + brow + c1);
            mma_bf16(acc[n], ah0, ah1, ah2, ah3, bh0, bh1);
            mma_bf16(acc[n], ah0, ah1, ah2, ah3, bl0, bl1);
            mma_bf16(acc[n], al0, al1, al2, al3, bh0, bh1);
        }
    }
    __syncthreads();

    float* stage = reinterpret_cast<float*>(dsm);
    {
        #pragma unroll
        for (int n = 0; n < 12; n++) {
            int c = n * 8 + 2 * tg;
            float2* p0 = reinterpret_cast<float2*>(&stage[(m0 + g) * STRIDE_ST + c]);
            float2* p1 = reinterpret_cast<float2*>(&stage[(m0 + g + 8) * STRIDE_ST + c]);
            *p0 = make_float2(acc[n][0], acc[n][1]);
            *p1 = make_float2(acc[n][2], acc[n][3]);
        }
    }
    __syncthreads();

    // ---- coalesced fp16 store with bias add (8 halves per thread per iter) ----
    {
        uint4* outp = reinterpret_cast<uint4*>(xg + base * G_);
        #pragma unroll
        for (int it = 0; it < PM * G_ / 8 / 256; it++) {
            int i = tid + it * 256;
            int e = 8 * i;
            int r = e / G_, c = e % G_;
            const float* sp = &stage[r * STRIDE_ST + c];
            const float* bp = &sbias[c];
            uint4 v;
            __half2 h0 = __floats2half2_rn(sp[0] + bp[0], sp[1] + bp[1]);
            __half2 h1 = __floats2half2_rn(sp[2] + bp[2], sp[3] + bp[3]);
            __half2 h2 = __floats2half2_rn(sp[4] + bp[4], sp[5] + bp[5]);
            __half2 h3 = __floats2half2_rn(sp[6] + bp[6], sp[7] + bp[7]);
            v.x = *reinterpret_cast<uint32_t*>(&h0);
            v.y = *reinterpret_cast<uint32_t*>(&h1);
            v.z = *reinterpret_cast<uint32_t*>(&h2);
            v.w = *reinterpret_cast<uint32_t*>(&h3);
            outp[i] = v;
        }
    }
}

// ================= Phase 2: recurrence (warp/row, 16-slot cp.async ring, f32x2) =============
#define WARPS_P2 4
#define NSLOT 16
#define PF 15
#define STEPB (G_ * 2)     // bytes per step (96 halves = 192B)

__global__ __launch_bounds__(32 * WARPS_P2, 4)
void gru_kernel(const __half* __restrict__ xg,
                const float* __restrict__ W_hh,
                const float* __restrict__ b_hh,
                const float* __restrict__ W_head,
                const float* __restrict__ b_head,
                float* __restrict__ out)
{
    __shared__ __align__(16) __half ring[WARPS_P2][NSLOT][G_];
    __shared__ __align__(16) float sh[WARPS_P2][2][H_];

    const int wid = threadIdx.x >> 5;
    const int j   = threadIdx.x & 31;
    const int row = blockIdx.x * WARPS_P2 + wid;

    // per-lane recurrent weights as f32x2 pairs
    uint64_t Wr2[H_ / 2], Wz2[H_ / 2], Wn2[H_ / 2];
    {
        const ulonglong2* pr = reinterpret_cast<const ulonglong2*>(W_hh + (j)          * H_);
        const ulonglong2* pz = reinterpret_cast<const ulonglong2*>(W_hh + (H_ + j)     * H_);
        const ulonglong2* pn = reinterpret_cast<const ulonglong2*>(W_hh + (2 * H_ + j) * H_);
        #pragma unroll
        for (int i = 0; i < H_ / 4; i++) {
            ulonglong2 a = pr[i], b = pz[i], c = pn[i];
            Wr2[2*i] = a.x; Wr2[2*i+1] = a.y;
            Wz2[2*i] = b.x; Wz2[2*i+1] = b.y;
            Wn2[2*i] = c.x; Wn2[2*i+1] = c.y;
        }
    }
    const uint64_t br2 = (uint64_t)__float_as_uint(b_hh[j]);
    const uint64_t bz2 = (uint64_t)__float_as_uint(b_hh[H_ + j]);
    const uint64_t bn2 = (uint64_t)__float_as_uint(b_hh[2 * H_ + j]);

    const __half* xp = xg + (size_t)row * T_ * G_;
    const uint32_t rb = smem_u32(&ring[wid][0][0]);

    // preload slots 0..PF-1 (192B each: lanes 0-11 copy 16B)
    #pragma unroll
    for (int p = 0; p < PF; p++) {
        if (j < 12) {
            uint32_t dst = rb + (uint32_t)p * STEPB + j * 16;
            const __half* src = xp + p * G_ + j * 8;
            asm volatile("cp.async.cg.shared.global [%0], [%1], 16;" :: "r"(dst), "l"(src));
        }
        asm volatile("cp.async.commit_group;" ::: "memory");
    }

    sh[wid][0][j] = 0.f;
    float h = 0.f;
    __syncwarp();

    #pragma unroll 1
    for (int t = 0; t < T_; t++) {
        {
            int ft = t + PF;
            if (ft < T_ && j < 12) {
                uint32_t dst = rb + (uint32_t)(ft & (NSLOT - 1)) * STEPB + j * 16;
                const __half* src = xp + (size_t)ft * G_ + j * 8;
                asm volatile("cp.async.cg.shared.global [%0], [%1], 16;" :: "r"(dst), "l"(src));
            }
            asm volatile("cp.async.commit_group;" ::: "memory");
            asm volatile("cp.async.wait_group 14;" ::: "memory");
            __syncwarp();
        }

        const __half* xs = &ring[wid][t & (NSLOT - 1)][0];
        float xr = __half2float(xs[j]);
        float xz = __half2float(xs[H_ + j]);
        float xn = __half2float(xs[2 * H_ + j]);

        // 6 accumulator chains (depth 8 each)
        const ulonglong2* hp = reinterpret_cast<const ulonglong2*>(sh[wid][t & 1]);
        uint64_t ar0 = br2, ar1 = 0ull;
        uint64_t az0 = bz2, az1 = 0ull;
        uint64_t an0 = bn2, an1 = 0ull;
        #pragma unroll
        for (int i = 0; i < H_ / 4; i++) {
            ulonglong2 hv = hp[i];
            ar0 = ffma2(hv.x, Wr2[2*i],   ar0);
            az0 = ffma2(hv.x, Wz2[2*i],   az0);
            an0 = ffma2(hv.x, Wn2[2*i],   an0);
            ar1 = ffma2(hv.y, Wr2[2*i+1], ar1);
            az1 = ffma2(hv.y, Wz2[2*i+1], az1);
            an1 = ffma2(hv.y, Wn2[2*i+1], an1);
        }
        float arf = (f2lo(ar0) + f2hi(ar0)) + (f2lo(ar1) + f2hi(ar1));
        float azf = (f2lo(az0) + f2hi(az0)) + (f2lo(az1) + f2hi(az1));
        float anf = (f2lo(an0) + f2hi(an0)) + (f2lo(an1) + f2hi(an1));

        float r = sigmoid_fast(xr + arf);
        float z = sigmoid_fast(xz + azf);
        float n = tanh_fast(fmaf(r, anf, xn));
        h = fmaf(z, h - n, n);

        sh[wid][(t + 1) & 1][j] = h;
        __syncwarp();
    }

    float v = h * W_head[j];
    #pragma unroll
    for (int o = 16; o > 0; o >>= 1)
        v += __shfl_xor_sync(0xffffffffu, v, o);
    if (j == 0)
        out[row] = sigmoid_fast(v + b_head[0]);
}

extern "C" void kernel_launch(void* const* d_in, const int* in_sizes, int n_in,
                              void* d_out, int out_size)
{
    const float* x      = (const float*)d_in[0];
    const float* W_ih   = (const float*)d_in[1];
    const float* W_hh   = (const float*)d_in[2];
    const float* b_ih   = (const float*)d_in[3];
    const float* b_hh   = (const float*)d_in[4];
    const float* W_head = (const float*)d_in[5];
    const float* b_head = (const float*)d_in[6];
    float* out = (float*)d_out;

    __half* xg;
    cudaGetSymbolAddress((void**)&xg, g_xg);

    cudaFuncSetAttribute(proj_kernel, cudaFuncAttributeMaxDynamicSharedMemorySize, SMEM_P1);
    proj_kernel<<<(B_ * T_) / PM, 256, SMEM_P1>>>(x, W_ih, b_ih, xg);
    gru_kernel<<<B_ / WARPS_P2, 32 * WARPS_P2>>>(xg, W_hh, b_hh, W_head, b_head, out);
}